// round 16
// baseline (speedup 1.0000x reference)
#include <cuda_runtime.h>
#include <cuda_bf16.h>
#include <math.h>
#include <stdint.h>

// ---------------- scratch (no allocations allowed) ----------------
#define NGMAX   4096        // max local genes
#define GCAP    1024        // bucket capacity per gene (mean ~250, sigma ~16)
#define NCGMAX  2048000     // max n_cells * n_genes
#define NCELLMAX 65536      // cell index fits 16 bits

__device__ int    d_hist[NGMAX];             // per-gene cut count / cursor
__device__ int2   d_info[NGMAX * GCAP];      // bucketed: {cell | (g2<<16), coord bits}
__device__ int    d_counts[NCGMAX];
__device__ float4 d_prm[NGMAX * 32];         // {loc, 1/scale, -log(scale)-0.5*log(2pi), logit_w}
__device__ uint32_t d_latbf[NCELLMAX * 32];  // latent rows as bf16x2 (128 B per cell)
__device__ uint32_t d_rwbf[NGMAX * 32];      // gathered rho_weight rows as bf16x2 (64 B per gene... 32 u32)
__device__ float2 d_rbl[NGMAX];              // per gene: {rho_bias, log(rho_bias)}
__device__ double d_acc;                     // likelihood accumulator

__device__ __forceinline__ uint32_t pack_bf16(float lo, float hi) {
    uint32_t r;
    asm("cvt.rn.bf16x2.f32 %0, %1, %2;" : "=r"(r) : "f"(hi), "f"(lo));
    return r;
}

// 256-bit load (Blackwell): two adjacent float4s in one instruction.
__device__ __forceinline__ void ldg256(const float4* p, float4& a, float4& b) {
    asm("ld.global.v8.f32 {%0,%1,%2,%3,%4,%5,%6,%7}, [%8];"
        : "=f"(a.x), "=f"(a.y), "=f"(a.z), "=f"(a.w),
          "=f"(b.x), "=f"(b.y), "=f"(b.z), "=f"(b.w)
        : "l"(p));
}

// Poisson term: fe = rb*exp(rho)*lib ; lf = -fe + [cnt>0] (cnt*(lrb+llib+rho) - lgamma(cnt+1))
// exp(rho) via degree-5 Taylor: |rho| <= ~0.1 -> rel err < 1e-7 (exact at fp32 level).
__device__ __forceinline__ float pois(float rho, float rb, float lrb,
                                      float lib, float llib, int cnt,
                                      const float* lgam) {
    float e = fmaf(rho, 0.2f, 1.0f);
    e = fmaf(rho * 0.25f, e, 1.0f);
    e = fmaf(rho * (1.0f / 3.0f), e, 1.0f);
    e = fmaf(rho * 0.5f, e, 1.0f);
    e = fmaf(rho, e, 1.0f);
    float lf = -rb * e * lib;
    if (cnt)
        lf += (float)cnt * (lrb + llib + rho) - (cnt < 32 ? lgam[cnt] : lgammaf((float)cnt + 1.0f));
    return lf;
}

// ---------------- kernels ----------------

// zero scratch (hist, counts, accumulators) — must precede k_gather
__global__ void k_zero(int ncg, int ng) {
    int i = blockIdx.x * blockDim.x + threadIdx.x;
    int stride = gridDim.x * blockDim.x;
    int ncg4 = ncg >> 2;
    int4* c4 = (int4*)d_counts;
    int4 z4 = make_int4(0, 0, 0, 0);
    for (int j = i; j < ncg4; j += stride) c4[j] = z4;
    for (int j = (ncg4 << 2) + i; j < ncg; j += stride) d_counts[j] = 0;
    for (int j = i; j < ng; j += stride) d_hist[j] = 0;
    if (i == 0) d_acc = 0.0;
}

// gathered per-gene parameter tables + bf16 latent/rho_weight (indep of k_zero)
__global__ void k_ztables(const int* __restrict__ genes_oi,
                          const float* __restrict__ loc_w,
                          const float* __restrict__ scale_w,
                          const float* __restrict__ logit_w,
                          const float* __restrict__ rho_weight,
                          const float* __restrict__ rho_bias,
                          const float* __restrict__ latent,
                          int n_cells, int ng) {
    int i = blockIdx.x * blockDim.x + threadIdx.x;
    int stride = gridDim.x * blockDim.x;
    for (int j = i; j < ng * 32; j += stride) {
        int g = j >> 5, c = j & 31;
        int gene = genes_oi[g];
        float lwv = logit_w[gene * 32 + c];
        float loc = 1.0f / (1.0f + expf(-loc_w[gene * 32 + c]));
        float sc  = 1e-5f + expf(scale_w[gene * 32 + c]);
        d_prm[j] = make_float4(loc, 1.0f / sc, -logf(sc) - 0.91893853320467274f, lwv);
    }
    // rho_weight rows -> bf16x2 (K-contiguous per gene)
    for (int j = i; j < ng * 32; j += stride) {
        int g = j >> 5, h = j & 31;
        const float* rp = rho_weight + (size_t)genes_oi[g] * 64 + 2 * h;
        d_rwbf[j] = pack_bf16(rp[0], rp[1]);
    }
    for (int j = i; j < ng; j += stride) {
        float rb = rho_bias[genes_oi[j]];
        d_rbl[j] = make_float2(rb, logf(rb));
    }
    for (int j = i; j < n_cells * 32; j += stride) {
        float2 v = *(const float2*)(latent + 2 * j);
        d_latbf[j] = pack_bf16(v.x, v.y);
    }
}

// Fused gather: direct-bucket scatter of cuts by gene + fragment histogram.
// x4 ILP via vector loads to pipeline atomic latency.
__global__ void __launch_bounds__(512) k_gather(
        const int* __restrict__ clcg,
        const int* __restrict__ clg,
        const float* __restrict__ coords,
        const int* __restrict__ lcg,
        int n_cuts, int n_frags, int ng) {
    int i0 = blockIdx.x * blockDim.x + threadIdx.x;
    int stride = gridDim.x * blockDim.x;
    int nc4 = n_cuts >> 2;
    for (int q = i0; q < nc4; q += stride) {
        int4 v4 = ((const int4*)clcg)[q];
        int4 g4 = ((const int4*)clg)[q];
        float4 x4 = ((const float4*)coords)[q];
        int ga = v4.x % ng, gb = v4.y % ng, gc = v4.z % ng, gd = v4.w % ng;
        int pa = atomicAdd(&d_hist[ga], 1);
        int pb = atomicAdd(&d_hist[gb], 1);
        int pc = atomicAdd(&d_hist[gc], 1);
        int pd = atomicAdd(&d_hist[gd], 1);
        if (pa < GCAP) d_info[(ga << 10) + pa] = make_int2((v4.x / ng) | (g4.x << 16), __float_as_int(x4.x));
        if (pb < GCAP) d_info[(gb << 10) + pb] = make_int2((v4.y / ng) | (g4.y << 16), __float_as_int(x4.y));
        if (pc < GCAP) d_info[(gc << 10) + pc] = make_int2((v4.z / ng) | (g4.z << 16), __float_as_int(x4.z));
        if (pd < GCAP) d_info[(gd << 10) + pd] = make_int2((v4.w / ng) | (g4.w << 16), __float_as_int(x4.w));
    }
    for (int k = (nc4 << 2) + i0; k < n_cuts; k += stride) {
        int v = clcg[k];
        int g = v % ng;
        int p = atomicAdd(&d_hist[g], 1);
        if (p < GCAP)
            d_info[(g << 10) + p] = make_int2((v / ng) | (clg[k] << 16), __float_as_int(coords[k]));
    }
    int nf4 = n_frags >> 2;
    for (int q = i0; q < nf4; q += stride) {
        int4 f4 = ((const int4*)lcg)[q];
        atomicAdd(&d_counts[f4.x], 1);
        atomicAdd(&d_counts[f4.y], 1);
        atomicAdd(&d_counts[f4.z], 1);
        atomicAdd(&d_counts[f4.w], 1);
    }
    for (int f = (nf4 << 2) + i0; f < n_frags; f += stride)
        atomicAdd(&d_counts[lcg[f]], 1);
}

// Mixture log-likelihood via tensor cores (unchanged from R15 — validated).
__global__ void __launch_bounds__(256, 4) k_mix(
        const int* __restrict__ genes_oi,
        const float* __restrict__ logit_weight,
        int ng) {
    __shared__ uint32_t sbB[4 * 4 * 32 * 2];            // 4 KB, [ks][ns][lane][j]
    __shared__ __align__(16) unsigned char sA[8][2048]; // 16 KB: 16 rows x 128 B per warp
    __shared__ float wpart[8];
    int g = blockIdx.x;
    int lane = threadIdx.x & 31;
    int w = threadIdx.x >> 5;

    const float* lwg = logit_weight + (size_t)genes_oi[g] * 2048;

    for (int idx = threadIdx.x; idx < 1024; idx += 256) {
        int j  = idx & 1;
        int le = (idx >> 1) & 31;
        int ns = (idx >> 6) & 3;
        int ks = idx >> 8;
        int c  = ns * 8 + (le >> 2);
        int k0 = ks * 16 + (le & 3) * 2 + j * 8;
        sbB[idx] = pack_bf16(lwg[k0 * 32 + c], lwg[(k0 + 1) * 32 + c]);
    }
    int cnt = min(d_hist[g], GCAP);
    int s0 = g << 10;
    int s1 = s0 + cnt;
    __syncthreads();

    float acc = 0.0f;
    int r  = lane >> 2;
    int cq = (lane & 3) * 2;
    uint32_t wb = (uint32_t)__cvta_generic_to_shared(sA[w]);
    int lm_row = ((lane >> 3) & 1) * 8 + (lane & 7);
    int lm_half = lane >> 4;

    for (int ts = s0 + 16 * w; ts < s1; ts += 128) {
        int n = min(16, s1 - ts);

        int ix = 0;
        float xl = 0.0f;
        if (lane < 16 && ts + lane < s1) {
            int2 ii = d_info[ts + lane];
            ix = ii.x;
            xl = __int_as_float(ii.y);
        }

        __syncwarp();
#pragma unroll
        for (int it = 0; it < 4; it++) {
            int q = it * 32 + lane;
            int row = q >> 3, ch = q & 7;
            int cell = __shfl_sync(0xffffffffu, ix, row) & 0xffff;
            uint4 v = *((const uint4*)d_latbf + cell * 8 + ch);
            uint32_t ad = wb + row * 128 + ((ch ^ (row & 7)) << 4);
            asm volatile("st.shared.v4.b32 [%0], {%1,%2,%3,%4};"
                         :: "r"(ad), "r"(v.x), "r"(v.y), "r"(v.z), "r"(v.w));
        }
        __syncwarp();

        float d[4][4];
#pragma unroll
        for (int ns = 0; ns < 4; ns++)
#pragma unroll
            for (int j = 0; j < 4; j++) d[ns][j] = 0.0f;

#pragma unroll
        for (int ks = 0; ks < 4; ks++) {
            int chunk = ks * 2 + lm_half;
            uint32_t ad = wb + lm_row * 128 + ((chunk ^ (lm_row & 7)) << 4);
            uint32_t a0, a1, a2, a3;
            asm volatile("ldmatrix.sync.aligned.m8n8.x4.shared.b16 {%0,%1,%2,%3}, [%4];"
                         : "=r"(a0), "=r"(a1), "=r"(a2), "=r"(a3) : "r"(ad));
#pragma unroll
            for (int ns = 0; ns < 4; ns++) {
                uint2 bb = *(const uint2*)&sbB[((ks * 4 + ns) * 32 + lane) * 2];
                asm volatile(
                    "mma.sync.aligned.m16n8k16.row.col.f32.bf16.bf16.f32 "
                    "{%0,%1,%2,%3}, {%4,%5,%6,%7}, {%8,%9}, {%0,%1,%2,%3};"
                    : "+f"(d[ns][0]), "+f"(d[ns][1]), "+f"(d[ns][2]), "+f"(d[ns][3])
                    : "r"(a0), "r"(a1), "r"(a2), "r"(a3), "r"(bb.x), "r"(bb.y));
            }
        }

        int ixA = __shfl_sync(0xffffffffu, ix, r);
        int ixB = __shfl_sync(0xffffffffu, ix, r + 8);
        float xA = __shfl_sync(0xffffffffu, xl, r);
        float xB = __shfl_sync(0xffffffffu, xl, r + 8);
        const float4* prmA = d_prm + (((unsigned)ixA) >> 16) * 32;
        const float4* prmB = d_prm + (((unsigned)ixB) >> 16) * 32;
        float eaA = 0.f, ebA = 0.f, eaB = 0.f, ebB = 0.f;
#pragma unroll
        for (int ns = 0; ns < 4; ns++) {
            int c0 = ns * 8 + cq;
            float4 pa0, pa1, pb0, pb1;
            ldg256(prmA + c0, pa0, pa1);
            ldg256(prmB + c0, pb0, pb1);
            float la, z, lb;
            la = d[ns][0] + pa0.w; z = (xA - pa0.x) * pa0.y;
            lb = fmaf(-0.5f * z, z, la + pa0.z);
            eaA += __expf(la); ebA += __expf(lb);
            la = d[ns][1] + pa1.w; z = (xA - pa1.x) * pa1.y;
            lb = fmaf(-0.5f * z, z, la + pa1.z);
            eaA += __expf(la); ebA += __expf(lb);
            la = d[ns][2] + pb0.w; z = (xB - pb0.x) * pb0.y;
            lb = fmaf(-0.5f * z, z, la + pb0.z);
            eaB += __expf(la); ebB += __expf(lb);
            la = d[ns][3] + pb1.w; z = (xB - pb1.x) * pb1.y;
            lb = fmaf(-0.5f * z, z, la + pb1.z);
            eaB += __expf(la); ebB += __expf(lb);
        }
        eaA += __shfl_xor_sync(0xffffffffu, eaA, 1);
        ebA += __shfl_xor_sync(0xffffffffu, ebA, 1);
        eaB += __shfl_xor_sync(0xffffffffu, eaB, 1);
        ebB += __shfl_xor_sync(0xffffffffu, ebB, 1);
        eaA += __shfl_xor_sync(0xffffffffu, eaA, 2);
        ebA += __shfl_xor_sync(0xffffffffu, ebA, 2);
        eaB += __shfl_xor_sync(0xffffffffu, eaB, 2);
        ebB += __shfl_xor_sync(0xffffffffu, ebB, 2);
        if ((lane & 3) == 0) {
            if (r < n)     acc += __logf(ebA) - __logf(eaA);
            if (r + 8 < n) acc += __logf(ebB) - __logf(eaB);
        }
    }

#pragma unroll
    for (int o = 16; o > 0; o >>= 1) acc += __shfl_xor_sync(0xffffffffu, acc, o);
    if (lane == 0) wpart[w] = acc;
    __syncthreads();
    if (threadIdx.x == 0) {
        float b = 0.f;
#pragma unroll
        for (int i = 0; i < 8; i++) b += wpart[i];
        atomicAdd(&d_acc, (double)b);
    }
}

// Fragment-count Poisson likelihood via tensor cores:
// CTA = 64 genes x 128 cells; warp = 16 cells (M) x 64 genes (N), 32 mma.
// rho = latbf[cells,64] x rwbf[genes,64]^T. exp via Taylor (|rho|<0.1),
// log(fe) decomposed exactly as log(rbg)+log(lib)+rho -> zero MUFU mainline.
#define FG 64
#define FC 128
__global__ void __launch_bounds__(256) k_fragmma(
        const float* __restrict__ libsize,
        const int* __restrict__ cells_oi,
        int n_cells, int ng, int ngt) {
    __shared__ uint32_t sbB[4 * 8 * 32 * 2];   // 8 KB
    __shared__ float lib_s[FC], llib_s[FC];
    __shared__ float lgam[32];
    __shared__ float wpart[8];
    int gb = blockIdx.x % ngt;
    int cb = blockIdx.x / ngt;
    int g0 = gb * FG, c0 = cb * FC;
    int tid = threadIdx.x, lane = tid & 31, w = tid >> 5;

    if (tid < 32) lgam[tid] = lgammaf((float)tid + 1.0f);
    for (int i = tid; i < FC; i += 256) {
        int cell = c0 + i;
        float lv = 1.0f, llv = 0.0f;
        if (cell < n_cells) { lv = libsize[cells_oi[cell]]; llv = __logf(lv); }
        lib_s[i] = lv; llib_s[i] = llv;
    }
    // B table (same proven layout as k_mix): idx = ((ks*8+ns)*32+le)*2+j,
    // gene = g0+ns*8+(le>>2), val = rwbf[gene] uint at 8*ks+(le&3)+4*j
    for (int idx = tid; idx < 2048; idx += 256) {
        int j  = idx & 1;
        int le = (idx >> 1) & 31;
        int ns = (idx >> 6) & 7;
        int ks = idx >> 9;
        int gene = g0 + ns * 8 + (le >> 2);
        sbB[idx] = (gene < ng) ? d_rwbf[gene * 32 + 8 * ks + (le & 3) + 4 * j] : 0u;
    }
    __syncthreads();

    int r = lane >> 2, cq = (lane & 3) * 2;
    int cA = c0 + w * 16 + r;
    int cB = cA + 8;
    const uint32_t* LA = d_latbf + (size_t)min(cA, n_cells - 1) * 32;
    const uint32_t* LB = d_latbf + (size_t)min(cB, n_cells - 1) * 32;

    float d[8][4];
#pragma unroll
    for (int ns = 0; ns < 8; ns++)
#pragma unroll
        for (int j = 0; j < 4; j++) d[ns][j] = 0.0f;

#pragma unroll
    for (int ks = 0; ks < 4; ks++) {
        uint32_t a0 = LA[8 * ks + (lane & 3)];
        uint32_t a1 = LB[8 * ks + (lane & 3)];
        uint32_t a2 = LA[8 * ks + 4 + (lane & 3)];
        uint32_t a3 = LB[8 * ks + 4 + (lane & 3)];
#pragma unroll
        for (int ns = 0; ns < 8; ns++) {
            uint2 bb = *(const uint2*)&sbB[((ks * 8 + ns) * 32 + lane) * 2];
            asm volatile(
                "mma.sync.aligned.m16n8k16.row.col.f32.bf16.bf16.f32 "
                "{%0,%1,%2,%3}, {%4,%5,%6,%7}, {%8,%9}, {%0,%1,%2,%3};"
                : "+f"(d[ns][0]), "+f"(d[ns][1]), "+f"(d[ns][2]), "+f"(d[ns][3])
                : "r"(a0), "r"(a1), "r"(a2), "r"(a3), "r"(bb.x), "r"(bb.y));
        }
    }

    bool okA = cA < n_cells, okB = cB < n_cells;
    float liA = lib_s[w * 16 + r],     llA = llib_s[w * 16 + r];
    float liB = lib_s[w * 16 + r + 8], llB = llib_s[w * 16 + r + 8];
    float acc = 0.0f;
#pragma unroll
    for (int ns = 0; ns < 8; ns++) {
        int gA = g0 + ns * 8 + cq;     // even (cq even, g0 mult of 64)
        if (gA + 1 < ng) {
            float4 rl = *(const float4*)(d_rbl + gA);   // {rb0,lrb0,rb1,lrb1}
            if (okA) {
                int2 cnt = *(const int2*)(d_counts + (size_t)cA * ng + gA);
                acc += pois(d[ns][0], rl.x, rl.y, liA, llA, cnt.x, lgam);
                acc += pois(d[ns][1], rl.z, rl.w, liA, llA, cnt.y, lgam);
            }
            if (okB) {
                int2 cnt = *(const int2*)(d_counts + (size_t)cB * ng + gA);
                acc += pois(d[ns][2], rl.x, rl.y, liB, llB, cnt.x, lgam);
                acc += pois(d[ns][3], rl.z, rl.w, liB, llB, cnt.y, lgam);
            }
        } else if (gA < ng) {          // single-gene edge (odd ng)
            float2 rl = d_rbl[gA];
            if (okA) acc += pois(d[ns][0], rl.x, rl.y, liA, llA,
                                 d_counts[(size_t)cA * ng + gA], lgam);
            if (okB) acc += pois(d[ns][2], rl.x, rl.y, liB, llB,
                                 d_counts[(size_t)cB * ng + gA], lgam);
        }
    }

#pragma unroll
    for (int o = 16; o > 0; o >>= 1) acc += __shfl_xor_sync(0xffffffffu, acc, o);
    if (lane == 0) wpart[w] = acc;
    __syncthreads();
    if (tid == 0) {
        float b = 0.f;
#pragma unroll
        for (int i = 0; i < 8; i++) b += wpart[i];
        atomicAdd(&d_acc, (double)b);
    }
}

// Final output write — after the mix/frag join.
__global__ void k_final(float* out) {
    if (threadIdx.x == 0) out[0] = (float)(-d_acc);
}

// ---------------- launch ----------------
extern "C" void kernel_launch(void* const* d_in, const int* in_sizes, int n_in,
                              void* d_out, int out_size) {
    const int*   lcg      = (const int*)d_in[0];    // local_cellxgene_ix [n_frags]
    const float* coords   = (const float*)d_in[1];  // cut_coordinates [n_cuts]
    const float* latent   = (const float*)d_in[2];  // [n_cells, 64]
    const int*   genes_oi = (const int*)d_in[3];    // [n_genes]
    const int*   cells_oi = (const int*)d_in[4];    // [n_cells]
    const int*   clcg     = (const int*)d_in[5];    // cut_local_cellxgene_ix [n_cuts]
    const int*   clg      = (const int*)d_in[6];    // cut_local_gene_ix [n_cuts]
    const float* loc_w    = (const float*)d_in[9];
    const float* scale_w  = (const float*)d_in[10];
    const float* logit_w  = (const float*)d_in[11];
    const float* lw       = (const float*)d_in[12]; // logit_weight [20000,64,32]
    const float* rw       = (const float*)d_in[13]; // rho_weight [20000,64]
    const float* rho_bias = (const float*)d_in[14];
    const float* libsize  = (const float*)d_in[15];

    int n_frags = in_sizes[0];
    int n_cuts  = in_sizes[1];
    int n_cells = in_sizes[2] / 64;
    int n_genes = in_sizes[3];
    int ncg = n_cells * n_genes;

    float* out = (float*)d_out;
    (void)n_in; (void)out_size;

    // Side stream + events for parallel branches in the captured graph.
    // Created per call, intentionally not destroyed (few calls; no dev mem).
    cudaStream_t sB;
    cudaEvent_t eFork1, eJoin1, eFork2, eJoin2;
    cudaStreamCreateWithFlags(&sB, cudaStreamNonBlocking);
    cudaEventCreateWithFlags(&eFork1, cudaEventDisableTiming);
    cudaEventCreateWithFlags(&eJoin1, cudaEventDisableTiming);
    cudaEventCreateWithFlags(&eFork2, cudaEventDisableTiming);
    cudaEventCreateWithFlags(&eJoin2, cudaEventDisableTiming);

    cudaStream_t s0 = 0;

    // fork: ztables runs parallel with zero+gather
    cudaEventRecord(eFork1, s0);
    cudaStreamWaitEvent(sB, eFork1, 0);
    k_ztables<<<256, 256, 0, sB>>>(genes_oi, loc_w, scale_w, logit_w, rw, rho_bias,
                                   latent, n_cells, n_genes);
    k_zero<<<256, 256>>>(ncg, n_genes);
    k_gather<<<148, 512>>>(clcg, clg, coords, lcg, n_cuts, n_frags, n_genes);
    cudaEventRecord(eJoin1, sB);
    cudaStreamWaitEvent(s0, eJoin1, 0);

    // fork: fragmma (tensor+FMA) runs parallel with mix (L1/MUFU)
    int ngt = (n_genes + FG - 1) / FG;
    int nfb = ngt * ((n_cells + FC - 1) / FC);
    cudaEventRecord(eFork2, s0);
    cudaStreamWaitEvent(sB, eFork2, 0);
    k_fragmma<<<nfb, 256, 0, sB>>>(libsize, cells_oi, n_cells, n_genes, ngt);
    k_mix<<<n_genes, 256>>>(genes_oi, lw, n_genes);
    cudaEventRecord(eJoin2, sB);
    cudaStreamWaitEvent(s0, eJoin2, 0);

    k_final<<<1, 32>>>(out);
}

// round 17
// speedup vs baseline: 1.2533x; 1.2533x over previous
#include <cuda_runtime.h>
#include <cuda_bf16.h>
#include <math.h>
#include <stdint.h>

// ---------------- scratch (no allocations allowed) ----------------
#define NGMAX   4096        // max local genes
#define GCAP    1024        // bucket capacity per gene (mean ~250, sigma ~16)
#define NCGMAX  2048000     // max n_cells * n_genes
#define NCELLMAX 65536      // cell index fits 16 bits

__device__ int    d_hist[NGMAX];             // per-gene cut count / cursor
__device__ int2   d_info[NGMAX * GCAP];      // bucketed: {cell | (g2<<16), coord bits}
__device__ int    d_counts[NCGMAX];
__device__ float4 d_prm[NGMAX * 32];         // {loc, 1/scale, -log(scale)-0.5*log(2pi), logit_w}
__device__ uint32_t d_latbf[NCELLMAX * 32];  // latent rows as bf16x2 (128 B per cell)
__device__ float  d_rwT[64 * NGMAX];         // gathered+transposed rho_weight: [l][g]
__device__ float  d_rbg[NGMAX];              // gathered rho_bias
__device__ double d_acc;                     // likelihood accumulator

__device__ __forceinline__ uint32_t pack_bf16(float lo, float hi) {
    uint32_t r;
    asm("cvt.rn.bf16x2.f32 %0, %1, %2;" : "=r"(r) : "f"(hi), "f"(lo));
    return r;
}

// 256-bit load (Blackwell): two adjacent float4s in one instruction.
__device__ __forceinline__ void ldg256(const float4* p, float4& a, float4& b) {
    asm("ld.global.v8.f32 {%0,%1,%2,%3,%4,%5,%6,%7}, [%8];"
        : "=f"(a.x), "=f"(a.y), "=f"(a.z), "=f"(a.w),
          "=f"(b.x), "=f"(b.y), "=f"(b.z), "=f"(b.w)
        : "l"(p));
}

// ---------------- kernels ----------------

// zero scratch (hist, counts, accumulators) — must precede k_gather
__global__ void k_zero(int ncg, int ng) {
    int i = blockIdx.x * blockDim.x + threadIdx.x;
    int stride = gridDim.x * blockDim.x;
    int ncg4 = ncg >> 2;
    int4* c4 = (int4*)d_counts;
    int4 z4 = make_int4(0, 0, 0, 0);
    for (int j = i; j < ncg4; j += stride) c4[j] = z4;
    for (int j = (ncg4 << 2) + i; j < ncg; j += stride) d_counts[j] = 0;
    for (int j = i; j < ng; j += stride) d_hist[j] = 0;
    if (i == 0) d_acc = 0.0;
}

// gathered per-gene parameter tables + bf16 latent (independent of k_zero)
__global__ void k_ztables(const int* __restrict__ genes_oi,
                          const float* __restrict__ loc_w,
                          const float* __restrict__ scale_w,
                          const float* __restrict__ logit_w,
                          const float* __restrict__ rho_weight,
                          const float* __restrict__ rho_bias,
                          const float* __restrict__ latent,
                          int n_cells, int ng) {
    int i = blockIdx.x * blockDim.x + threadIdx.x;
    int stride = gridDim.x * blockDim.x;
    for (int j = i; j < ng * 32; j += stride) {
        int g = j >> 5, c = j & 31;
        int gene = genes_oi[g];
        float lwv = logit_w[gene * 32 + c];
        float loc = 1.0f / (1.0f + expf(-loc_w[gene * 32 + c]));
        float sc  = 1e-5f + expf(scale_w[gene * 32 + c]);
        d_prm[j] = make_float4(loc, 1.0f / sc, -logf(sc) - 0.91893853320467274f, lwv);
    }
    for (int j = i; j < ng * 64; j += stride) {
        int g = j % ng, l = j / ng;
        d_rwT[l * ng + g] = rho_weight[(size_t)genes_oi[g] * 64 + l];
    }
    for (int j = i; j < ng; j += stride) d_rbg[j] = rho_bias[genes_oi[j]];
    for (int j = i; j < n_cells * 32; j += stride) {
        float2 v = *(const float2*)(latent + 2 * j);
        d_latbf[j] = pack_bf16(v.x, v.y);
    }
}

// Fused gather: direct-bucket scatter of cuts by gene + fragment histogram.
__global__ void __launch_bounds__(512) k_gather(
        const int* __restrict__ clcg,
        const int* __restrict__ clg,
        const float* __restrict__ coords,
        const int* __restrict__ lcg,
        int n_cuts, int n_frags, int ng) {
    int i0 = blockIdx.x * blockDim.x + threadIdx.x;
    int stride = gridDim.x * blockDim.x;
    for (int k = i0; k < n_cuts; k += stride) {
        int v = clcg[k];
        int g = v % ng;
        int cell = v / ng;
        int p = atomicAdd(&d_hist[g], 1);
        if (p < GCAP)
            d_info[(g << 10) + p] = make_int2(cell | (clg[k] << 16), __float_as_int(coords[k]));
    }
    for (int f = i0; f < n_frags; f += stride)
        atomicAdd(&d_counts[lcg[f]], 1);
}

// FUSED mix + frag kernel: one grid, dispatch on blockIdx.
//   blocks [0, ng):         mixture log-likelihood (tensor-core path, R15)
//   blocks [ng, ng+nfrag):  fragment Poisson likelihood (R14 fragfinal body)
// Both paths fit 64 regs / <=20.2 KB smem at (256,4), so frag CTAs co-reside
// with and fill the tail of the mix wave — true overlap without streams
// (stream overlap is impossible: mix at 4 CTAs x 256 thr x 64 regs = 100% RF).
#define CPB 8
#define NSPLIT 8
__global__ void __launch_bounds__(256, 4) k_mixfrag(
        const int* __restrict__ genes_oi,
        const float* __restrict__ logit_weight,
        const float* __restrict__ latent,
        const float* __restrict__ libsize,
        const int* __restrict__ cells_oi,
        int ng, int n_cells) {
    __shared__ uint32_t sbB[4 * 4 * 32 * 2];            // 4 KB
    __shared__ __align__(16) unsigned char sA[8][2048]; // 16 KB
    __shared__ float wpart[8];
    int lane = threadIdx.x & 31;
    int w = threadIdx.x >> 5;

    if (blockIdx.x < (unsigned)ng) {
        // ================= MIX PATH (identical to R15 k_mix) =================
        int g = blockIdx.x;
        const float* lwg = logit_weight + (size_t)genes_oi[g] * 2048;

        for (int idx = threadIdx.x; idx < 1024; idx += 256) {
            int j  = idx & 1;
            int le = (idx >> 1) & 31;
            int ns = (idx >> 6) & 3;
            int ks = idx >> 8;
            int c  = ns * 8 + (le >> 2);
            int k0 = ks * 16 + (le & 3) * 2 + j * 8;
            sbB[idx] = pack_bf16(lwg[k0 * 32 + c], lwg[(k0 + 1) * 32 + c]);
        }
        int cnt = min(d_hist[g], GCAP);
        int s0 = g << 10;
        int s1 = s0 + cnt;
        __syncthreads();

        float acc = 0.0f;
        int r  = lane >> 2;
        int cq = (lane & 3) * 2;
        uint32_t wb = (uint32_t)__cvta_generic_to_shared(sA[w]);
        int lm_row = ((lane >> 3) & 1) * 8 + (lane & 7);
        int lm_half = lane >> 4;

        for (int ts = s0 + 16 * w; ts < s1; ts += 128) {
            int n = min(16, s1 - ts);

            int ix = 0;
            float xl = 0.0f;
            if (lane < 16 && ts + lane < s1) {
                int2 ii = d_info[ts + lane];
                ix = ii.x;
                xl = __int_as_float(ii.y);
            }

            __syncwarp();
#pragma unroll
            for (int it = 0; it < 4; it++) {
                int q = it * 32 + lane;
                int row = q >> 3, ch = q & 7;
                int cell = __shfl_sync(0xffffffffu, ix, row) & 0xffff;
                uint4 v = *((const uint4*)d_latbf + cell * 8 + ch);
                uint32_t ad = wb + row * 128 + ((ch ^ (row & 7)) << 4);
                asm volatile("st.shared.v4.b32 [%0], {%1,%2,%3,%4};"
                             :: "r"(ad), "r"(v.x), "r"(v.y), "r"(v.z), "r"(v.w));
            }
            __syncwarp();

            float d[4][4];
#pragma unroll
            for (int ns = 0; ns < 4; ns++)
#pragma unroll
                for (int j = 0; j < 4; j++) d[ns][j] = 0.0f;

#pragma unroll
            for (int ks = 0; ks < 4; ks++) {
                int chunk = ks * 2 + lm_half;
                uint32_t ad = wb + lm_row * 128 + ((chunk ^ (lm_row & 7)) << 4);
                uint32_t a0, a1, a2, a3;
                asm volatile("ldmatrix.sync.aligned.m8n8.x4.shared.b16 {%0,%1,%2,%3}, [%4];"
                             : "=r"(a0), "=r"(a1), "=r"(a2), "=r"(a3) : "r"(ad));
#pragma unroll
                for (int ns = 0; ns < 4; ns++) {
                    uint2 bb = *(const uint2*)&sbB[((ks * 4 + ns) * 32 + lane) * 2];
                    asm volatile(
                        "mma.sync.aligned.m16n8k16.row.col.f32.bf16.bf16.f32 "
                        "{%0,%1,%2,%3}, {%4,%5,%6,%7}, {%8,%9}, {%0,%1,%2,%3};"
                        : "+f"(d[ns][0]), "+f"(d[ns][1]), "+f"(d[ns][2]), "+f"(d[ns][3])
                        : "r"(a0), "r"(a1), "r"(a2), "r"(a3), "r"(bb.x), "r"(bb.y));
                }
            }

            int ixA = __shfl_sync(0xffffffffu, ix, r);
            int ixB = __shfl_sync(0xffffffffu, ix, r + 8);
            float xA = __shfl_sync(0xffffffffu, xl, r);
            float xB = __shfl_sync(0xffffffffu, xl, r + 8);
            const float4* prmA = d_prm + (((unsigned)ixA) >> 16) * 32;
            const float4* prmB = d_prm + (((unsigned)ixB) >> 16) * 32;
            float eaA = 0.f, ebA = 0.f, eaB = 0.f, ebB = 0.f;
#pragma unroll
            for (int ns = 0; ns < 4; ns++) {
                int c0 = ns * 8 + cq;
                float4 pa0, pa1, pb0, pb1;
                ldg256(prmA + c0, pa0, pa1);
                ldg256(prmB + c0, pb0, pb1);
                float la, z, lb;
                la = d[ns][0] + pa0.w; z = (xA - pa0.x) * pa0.y;
                lb = fmaf(-0.5f * z, z, la + pa0.z);
                eaA += __expf(la); ebA += __expf(lb);
                la = d[ns][1] + pa1.w; z = (xA - pa1.x) * pa1.y;
                lb = fmaf(-0.5f * z, z, la + pa1.z);
                eaA += __expf(la); ebA += __expf(lb);
                la = d[ns][2] + pb0.w; z = (xB - pb0.x) * pb0.y;
                lb = fmaf(-0.5f * z, z, la + pb0.z);
                eaB += __expf(la); ebB += __expf(lb);
                la = d[ns][3] + pb1.w; z = (xB - pb1.x) * pb1.y;
                lb = fmaf(-0.5f * z, z, la + pb1.z);
                eaB += __expf(la); ebB += __expf(lb);
            }
            eaA += __shfl_xor_sync(0xffffffffu, eaA, 1);
            ebA += __shfl_xor_sync(0xffffffffu, ebA, 1);
            eaB += __shfl_xor_sync(0xffffffffu, eaB, 1);
            ebB += __shfl_xor_sync(0xffffffffu, ebB, 1);
            eaA += __shfl_xor_sync(0xffffffffu, eaA, 2);
            ebA += __shfl_xor_sync(0xffffffffu, ebA, 2);
            eaB += __shfl_xor_sync(0xffffffffu, eaB, 2);
            ebB += __shfl_xor_sync(0xffffffffu, ebB, 2);
            if ((lane & 3) == 0) {
                if (r < n)     acc += __logf(ebA) - __logf(eaA);
                if (r + 8 < n) acc += __logf(ebB) - __logf(eaB);
            }
        }

#pragma unroll
        for (int o = 16; o > 0; o >>= 1) acc += __shfl_xor_sync(0xffffffffu, acc, o);
        if (lane == 0) wpart[w] = acc;
        __syncthreads();
        if (threadIdx.x == 0) {
            float b = 0.f;
#pragma unroll
            for (int i = 0; i < 8; i++) b += wpart[i];
            atomicAdd(&d_acc, (double)b);
        }
    } else {
        // ================= FRAG PATH (identical to R14 k_fragfinal) =========
        // smem aliased into sA: lat_s[512] + lib_s[8]; lgam aliased into sbB.
        float* lat_s = (float*)sA;            // 2 KB
        float* lib_s = lat_s + CPB * 64;      // 32 B
        float* lgam  = (float*)sbB;           // 128 B

        int fb = blockIdx.x - ng;
        int cb = fb / NSPLIT;
        int qs = fb % NSPLIT;
        int c0 = cb * CPB;
        int nc = min(CPB, n_cells - c0);
        int g_lo = (int)(((long long)ng * qs) / NSPLIT) & ~1;
        int g_hi = (qs == NSPLIT - 1) ? ng : ((int)(((long long)ng * (qs + 1)) / NSPLIT) & ~1);
        if (threadIdx.x < 32) lgam[threadIdx.x] = lgammaf((float)threadIdx.x + 1.0f);
        for (int i = threadIdx.x; i < CPB * 64; i += blockDim.x)
            lat_s[i] = (i < nc * 64) ? latent[c0 * 64 + i] : 0.0f;
        if (threadIdx.x < CPB)
            lib_s[threadIdx.x] = (threadIdx.x < nc)
                ? libsize[cells_oi[min(c0 + threadIdx.x, n_cells - 1)]] : 1.0f;
        __syncthreads();

        float acc = 0.0f;
        int ngv = g_lo + ((g_hi - g_lo) & ~1);
        for (int gg = g_lo + threadIdx.x * 2; gg + 1 < ngv; gg += blockDim.x * 2) {
            float2 r2[CPB];
#pragma unroll
            for (int j = 0; j < CPB; j++) r2[j] = make_float2(0.f, 0.f);
#pragma unroll 8
            for (int l = 0; l < 64; l++) {
                float2 wv = *(const float2*)(d_rwT + l * ng + gg);
#pragma unroll
                for (int j = 0; j < CPB; j++) {
                    float lv = lat_s[j * 64 + l];
                    r2[j].x = fmaf(lv, wv.x, r2[j].x);
                    r2[j].y = fmaf(lv, wv.y, r2[j].y);
                }
            }
            float2 rb = *(const float2*)(d_rbg + gg);
#pragma unroll
            for (int j = 0; j < CPB; j++) {
                if (j >= nc) break;
                float lib = lib_s[j];
                int2 cnt = *(const int2*)(d_counts + (size_t)(c0 + j) * ng + gg);
                float fe, lf;
                fe = rb.x * __expf(r2[j].x) * lib; lf = -fe;
                if (cnt.x) lf += (float)cnt.x * __logf(fe) - (cnt.x < 32 ? lgam[cnt.x] : lgammaf((float)cnt.x + 1.0f));
                acc += lf;
                fe = rb.y * __expf(r2[j].y) * lib; lf = -fe;
                if (cnt.y) lf += (float)cnt.y * __logf(fe) - (cnt.y < 32 ? lgam[cnt.y] : lgammaf((float)cnt.y + 1.0f));
                acc += lf;
            }
        }
        // scalar tail genes of this split
        for (int gg = ngv + threadIdx.x; gg < g_hi; gg += blockDim.x) {
            for (int j = 0; j < nc; j++) {
                float rho = 0.f;
                for (int l = 0; l < 64; l++)
                    rho = fmaf(lat_s[j * 64 + l], d_rwT[l * ng + gg], rho);
                float fe = d_rbg[gg] * __expf(rho) * lib_s[j];
                int c = d_counts[(size_t)(c0 + j) * ng + gg];
                float lf = -fe;
                if (c) lf += (float)c * __logf(fe) - (c < 32 ? lgam[c] : lgammaf((float)c + 1.0f));
                acc += lf;
            }
        }

#pragma unroll
        for (int o = 16; o > 0; o >>= 1) acc += __shfl_xor_sync(0xffffffffu, acc, o);
        if (lane == 0) wpart[w] = acc;
        __syncthreads();
        if (threadIdx.x == 0) {
            float b = 0.f;
#pragma unroll
            for (int i = 0; i < 8; i++) b += wpart[i];
            atomicAdd(&d_acc, (double)b);
        }
    }
}

// Final output write.
__global__ void k_final(float* out) {
    if (threadIdx.x == 0) out[0] = (float)(-d_acc);
}

// ---------------- launch ----------------
extern "C" void kernel_launch(void* const* d_in, const int* in_sizes, int n_in,
                              void* d_out, int out_size) {
    const int*   lcg      = (const int*)d_in[0];    // local_cellxgene_ix [n_frags]
    const float* coords   = (const float*)d_in[1];  // cut_coordinates [n_cuts]
    const float* latent   = (const float*)d_in[2];  // [n_cells, 64]
    const int*   genes_oi = (const int*)d_in[3];    // [n_genes]
    const int*   cells_oi = (const int*)d_in[4];    // [n_cells]
    const int*   clcg     = (const int*)d_in[5];    // cut_local_cellxgene_ix [n_cuts]
    const int*   clg      = (const int*)d_in[6];    // cut_local_gene_ix [n_cuts]
    const float* loc_w    = (const float*)d_in[9];
    const float* scale_w  = (const float*)d_in[10];
    const float* logit_w  = (const float*)d_in[11];
    const float* lw       = (const float*)d_in[12]; // logit_weight [20000,64,32]
    const float* rw       = (const float*)d_in[13]; // rho_weight [20000,64]
    const float* rho_bias = (const float*)d_in[14];
    const float* libsize  = (const float*)d_in[15];

    int n_frags = in_sizes[0];
    int n_cuts  = in_sizes[1];
    int n_cells = in_sizes[2] / 64;
    int n_genes = in_sizes[3];
    int ncg = n_cells * n_genes;

    float* out = (float*)d_out;
    (void)n_in; (void)out_size;

    // Side stream + events so ztables runs parallel with zero+gather in the
    // captured graph. Created per call, intentionally not destroyed (few
    // calls; no device memory involved).
    cudaStream_t sB;
    cudaEvent_t eFork1, eJoin1;
    cudaStreamCreateWithFlags(&sB, cudaStreamNonBlocking);
    cudaEventCreateWithFlags(&eFork1, cudaEventDisableTiming);
    cudaEventCreateWithFlags(&eJoin1, cudaEventDisableTiming);

    cudaStream_t s0 = 0;

    cudaEventRecord(eFork1, s0);
    cudaStreamWaitEvent(sB, eFork1, 0);
    k_ztables<<<256, 256, 0, sB>>>(genes_oi, loc_w, scale_w, logit_w, rw, rho_bias,
                                   latent, n_cells, n_genes);
    k_zero<<<256, 256>>>(ncg, n_genes);
    k_gather<<<148, 512>>>(clcg, clg, coords, lcg, n_cuts, n_frags, n_genes);
    cudaEventRecord(eJoin1, sB);
    cudaStreamWaitEvent(s0, eJoin1, 0);

    // Fused mix+frag grid: frag blocks appended so they fill the mix tail.
    int nfrag = ((n_cells + CPB - 1) / CPB) * NSPLIT;
    k_mixfrag<<<n_genes + nfrag, 256>>>(genes_oi, lw, latent, libsize, cells_oi,
                                        n_genes, n_cells);

    k_final<<<1, 32>>>(out);
}